// round 14
// baseline (speedup 1.0000x reference)
#include <cuda_runtime.h>
#include <cooperative_groups.h>

namespace cg = cooperative_groups;

#define NG   512      // number of graphs
#define DIM  480      // feature dim
#define V    120      // float4 groups per row
#define NCH  224      // total channels (128 scalar + 64 l1 + 32 l2)
#define NSC  128      // scalar channels
#define EPSV 1e-5f
#define TPB  480      // 4 node-rows x 120 float4 lanes
#define ROWS 4
#define CSZ  4        // CTAs per cluster (one graph per cluster)

__device__ int g_off[NG + 1];   // g_off[g] = first node index with batch >= g

__device__ __forceinline__ int col_channel(int col) {
    if (col < 128) return col;                       // l=0
    if (col < 320) return 128 + (col - 128) / 3;     // l=1 (d=3)
    return 192 + (col - 320) / 5;                    // l=2 (d=5)
}

// Read batch id for node n under either dtype interpretation.
__device__ __forceinline__ int read_g(const void* __restrict__ b, int n, int is64) {
    if (is64) return (int)((const long long*)b)[n];
    return ((const int*)b)[n];
}

// batch sorted in [0, NG); N even. 32-bit word [N-1] is an odd index:
// int64 buffer -> high half == 0 ; int32 buffer -> batch[N-1] > 0 (w.p. ~1).
__device__ __forceinline__ int detect_is64(const void* __restrict__ b, int N) {
    return (((const int*)b)[N - 1] == 0) ? 1 : 0;
}

// ---------------------------------------------------------------------------
// Prep: boundary scan of sorted batch -> segment offsets g_off[0..NG].
// ---------------------------------------------------------------------------
__global__ void prep_kernel(const void* __restrict__ batch, int N) {
    const int is64 = detect_is64(batch, N);
    for (int n = blockIdx.x * blockDim.x + threadIdx.x; n < N;
         n += gridDim.x * blockDim.x) {
        int gn = read_g(batch, n, is64);
        if (n == 0) {
            for (int g = 0; g <= gn; g++) g_off[g] = 0;
        } else {
            int gp = read_g(batch, n - 1, is64);
            for (int g = gp + 1; g <= gn; g++) g_off[g] = n;
        }
        if (n == N - 1) {
            for (int g = gn + 1; g <= NG; g++) g_off[g] = N;
        }
    }
}

// ---------------------------------------------------------------------------
// Fused, 4-CTA clustered, occupancy-3: one GRAPH per cluster; each CTA
// handles a QUARTER slab (~187KB). Cross-round model:
//   * BW% rises with occupancy (R6 occ1 60% -> R12 occ4 66.9%) until
//     cluster-placement stranding bites (CSZ8: 57.6%).
//   * phase-B re-reads hit L2 iff T_A = slab/(SM_BW/occ) < ~15us turnover
//     (R10 9us hit / R12 21us miss / R13 10us hit).
// CSZ=4 + occ=3 is the cell that wins both: T_A~16us (borderline-safe),
// stranding same as the R10 record, +1 occupancy step for bubble overlap.
// launch_bounds(480,3) caps regs at 45 (R2's identical-shape loops needed
// 40), so the x2 manual unroll is dropped; 45 warps x 1 load in flight
// (23KB/SM) still covers the ~8KB latency-hiding requirement.
// Stores are __stcs (R11: __stwt breaks write-combining, +250MB RMW).
// ---------------------------------------------------------------------------
__global__ __launch_bounds__(TPB, 3) __cluster_dims__(CSZ, 1, 1)
void fused_kernel(
    const float4* __restrict__ in4, float4* __restrict__ out4,
    const float* __restrict__ w, const float* __restrict__ bias)
{
    __shared__ float s_sq[DIM];             // per-column partial sum of squares
    __shared__ float s_sum[NSC];            // per-column partial sum (scalars)
    __shared__ float s_scale[NCH], s_beta[NCH];
    __shared__ int s_range[4];              // mylo, myhi, glo, ghi

    cg::cluster_group cluster = cg::this_cluster();
    const unsigned rank = cluster.block_rank();   // 0..3
    const int g    = blockIdx.x / CSZ;
    const int tid  = threadIdx.x;
    const int lane = tid % V;
    const int row  = tid / V;
    const int col0 = lane * 4;
    const int c0 = col_channel(col0),     c1 = col_channel(col0 + 1);
    const int c2 = col_channel(col0 + 2), c3 = col_channel(col0 + 3);
    const bool sc = (col0 < NSC);

    if (tid == 0) {
        int glo = g_off[g], ghi = g_off[g + 1];
        int len = ghi - glo;
        s_range[0] = glo + (len * (int)rank) / CSZ;
        s_range[1] = glo + (len * ((int)rank + 1)) / CSZ;
        s_range[2] = glo;
        s_range[3] = ghi;
    }
    for (int i = tid; i < DIM; i += TPB) s_sq[i] = 0.f;
    for (int i = tid; i < NSC; i += TPB) s_sum[i] = 0.f;
    __syncthreads();

    const int lo = s_range[0], hi = s_range[1];
    const float4* __restrict__ base = in4 + lane;

    // ---- Phase A: accumulate partial stats over my quarter ----
    float q0 = 0.f, q1 = 0.f, q2 = 0.f, q3 = 0.f;
    float s0 = 0.f, s1 = 0.f, s2 = 0.f, s3 = 0.f;
    for (int n = lo + row; n < hi; n += ROWS) {
        float4 x = __ldg(base + (size_t)n * V);
        q0 = fmaf(x.x, x.x, q0); q1 = fmaf(x.y, x.y, q1);
        q2 = fmaf(x.z, x.z, q2); q3 = fmaf(x.w, x.w, q3);
        if (sc) { s0 += x.x; s1 += x.y; s2 += x.z; s3 += x.w; }
    }
    atomicAdd(&s_sq[col0 + 0], q0); atomicAdd(&s_sq[col0 + 1], q1);
    atomicAdd(&s_sq[col0 + 2], q2); atomicAdd(&s_sq[col0 + 3], q3);
    if (sc) {
        atomicAdd(&s_sum[col0 + 0], s0); atomicAdd(&s_sum[col0 + 1], s1);
        atomicAdd(&s_sum[col0 + 2], s2); atomicAdd(&s_sum[col0 + 3], s3);
    }

    // ---- Combine partials across the 4-CTA cluster ----
    cluster.sync();   // all ranks' partial stats visible cluster-wide

    if (tid < NCH) {
        const int t = tid;
        const float cntf = fmaxf((float)(s_range[3] - s_range[2]), 1.0f);
        float scale, beta;
        if (t < NSC) {
            float sm = 0.f, sq = 0.f;
            for (int r = 0; r < CSZ; r++) {
                sm += cluster.map_shared_rank(s_sum, r)[t];
                sq += cluster.map_shared_rank(s_sq,  r)[t];
            }
            float mean = sm / cntf;
            float var  = fmaxf(sq / cntf - mean * mean, 0.0f);
            scale = rsqrtf(var + EPSV) * w[t];
            beta  = bias[t] - mean * scale;
        } else if (t < 192) {
            int b0 = 128 + (t - 128) * 3;
            float sq = 0.f;
            for (int r = 0; r < CSZ; r++) {
                const float* p = cluster.map_shared_rank(s_sq, r);
                sq += p[b0] + p[b0 + 1] + p[b0 + 2];
            }
            scale = rsqrtf(sq / (3.0f * cntf) + EPSV) * w[t];
            beta  = 0.f;
        } else {
            int b0 = 320 + (t - 192) * 5;
            float sq = 0.f;
            for (int r = 0; r < CSZ; r++) {
                const float* p = cluster.map_shared_rank(s_sq, r);
                sq += p[b0] + p[b0 + 1] + p[b0 + 2] + p[b0 + 3] + p[b0 + 4];
            }
            scale = rsqrtf(sq / (5.0f * cntf) + EPSV) * w[t];
            beta  = 0.f;
        }
        s_scale[t] = scale;
        s_beta[t]  = beta;
    }

    // Params only need block-local visibility; s_sq is read-only from here.
    __syncthreads();

    // ---- Phase B: apply over my quarter (reads L2-hot; __stcs streaming) ----
    const float4 scv = make_float4(s_scale[c0], s_scale[c1], s_scale[c2], s_scale[c3]);
    const float4 btv = make_float4(s_beta[c0],  s_beta[c1],  s_beta[c2],  s_beta[c3]);
    float4* __restrict__ obase = out4 + lane;
    for (int n = lo + row; n < hi; n += ROWS) {
        float4 x = __ldcs(base + (size_t)n * V);
        float4 o;
        o.x = fmaf(x.x, scv.x, btv.x); o.y = fmaf(x.y, scv.y, btv.y);
        o.z = fmaf(x.z, scv.z, btv.z); o.w = fmaf(x.w, scv.w, btv.w);
        __stcs(obase + (size_t)n * V, o);
    }

    // SMEM-lifetime safety: peers' DSMEM reads of my partials must complete
    // before my SMEM is recycled. All quarters finish nearly together.
    cluster.sync();
}

// ---------------------------------------------------------------------------
extern "C" void kernel_launch(void* const* d_in, const int* in_sizes, int n_in,
                              void* d_out, int out_size)
{
    const float* inp   = (const float*)d_in[0];   // (N, 480) f32
    const float* w     = (const float*)d_in[1];   // (224,)   f32
    const float* bias  = (const float*)d_in[2];   // (128,)   f32
    const void*  batch = (const void*)d_in[3];    // (N,) int32 or int64, sorted
    float*       out   = (float*)d_out;

    const int N = in_sizes[0] / DIM;              // dtype-independent node count

    prep_kernel<<<304, 256>>>(batch, N);
    fused_kernel<<<NG * CSZ, TPB>>>((const float4*)inp, (float4*)out, w, bias);
}

// round 15
// speedup vs baseline: 1.0247x; 1.0247x over previous
#include <cuda_runtime.h>
#include <cooperative_groups.h>

namespace cg = cooperative_groups;

#define NG   512      // number of graphs
#define DIM  480      // feature dim
#define V    120      // float4 groups per row
#define NCH  224      // total channels (128 scalar + 64 l1 + 32 l2)
#define NSC  128      // scalar channels
#define EPSV 1e-5f
#define TPB  480      // 4 node-rows x 120 float4 lanes
#define ROWS 4
#define CSZ  4        // CTAs per cluster (one graph per cluster)

__device__ __forceinline__ int col_channel(int col) {
    if (col < 128) return col;                       // l=0
    if (col < 320) return 128 + (col - 128) / 3;     // l=1 (d=3)
    return 192 + (col - 320) / 5;                    // l=2 (d=5)
}

// Read batch id for node n under either dtype interpretation.
__device__ __forceinline__ int read_g(const void* __restrict__ b, int n, int is64) {
    if (is64) return (int)__ldg(((const long long*)b) + n);
    return __ldg(((const int*)b) + n);
}

// batch sorted in [0, NG); N even. 32-bit word [N-1] is an odd index:
// int64 buffer -> high half == 0 ; int32 buffer -> batch[N-1] > 0 (w.p. ~1).
__device__ __forceinline__ int detect_is64(const void* __restrict__ b, int N) {
    return (__ldg(((const int*)b) + (N - 1)) == 0) ? 1 : 0;
}

// First index n with batch[n] >= key (batch sorted ascending).
__device__ __forceinline__ int lower_bound_g(const void* __restrict__ b,
                                             int n, int key, int is64) {
    int lo = 0, hi = n;
    while (lo < hi) {
        int mid = (lo + hi) >> 1;
        if (read_g(b, mid, is64) < key) lo = mid + 1; else hi = mid;
    }
    return lo;
}

// ---------------------------------------------------------------------------
// Fused, 4-CTA clustered, occupancy-2 (= the R10 optimum of the cross-round
// landscape: T_A = slab/(SM_BW/occ) ~ 11us < L2 turnover ~20-25us -> phase-B
// re-reads L2-hit; occ=2 + unroll x2 carries 30KB/SM in flight, covering
// DRAM latency). Changes vs R10:
//   1. No prep kernel: each CTA binary-searches its own graph bounds on the
//      sorted batch (2 x 18-level lower_bound; tree top L2-caches at once).
//      Removes the prep kernel + two launch gaps (~6us of the 7.9us
//      total-minus-fused overhead).
//   2. Phase B iterates in REVERSE (LIFO): newest phase-A lines re-read
//      first -> strictly better L2 hit odds for marginal-age lines (Jensen).
// Stores are __stcs (R11: __stwt breaks write-combining, +250MB RMW).
// ---------------------------------------------------------------------------
__global__ __launch_bounds__(TPB, 2) __cluster_dims__(CSZ, 1, 1)
void fused_kernel(
    const float4* __restrict__ in4, float4* __restrict__ out4,
    const float* __restrict__ w, const float* __restrict__ bias,
    const void* __restrict__ batch, int N)
{
    __shared__ float s_sq[DIM];             // per-column partial sum of squares
    __shared__ float s_sum[NSC];            // per-column partial sum (scalars)
    __shared__ float s_scale[NCH], s_beta[NCH];
    __shared__ int s_bounds[2];             // glo, ghi for my graph

    cg::cluster_group cluster = cg::this_cluster();
    const unsigned rank = cluster.block_rank();   // 0..3
    const int g    = blockIdx.x / CSZ;
    const int tid  = threadIdx.x;
    const int lane = tid % V;
    const int row  = tid / V;
    const int col0 = lane * 4;
    const int c0 = col_channel(col0),     c1 = col_channel(col0 + 1);
    const int c2 = col_channel(col0 + 2), c3 = col_channel(col0 + 3);
    const bool sc = (col0 < NSC);

    // Per-CTA graph bounds via binary search on the sorted batch array.
    // Threads 0 and 1 search in parallel; ~18 L2-mostly-hit loads each.
    if (tid < 2) {
        int is64 = detect_is64(batch, N);
        s_bounds[tid] = lower_bound_g(batch, N, g + tid, is64);
    }
    for (int i = tid; i < DIM; i += TPB) s_sq[i] = 0.f;
    for (int i = tid; i < NSC; i += TPB) s_sum[i] = 0.f;
    __syncthreads();

    const int glo = s_bounds[0], ghi = s_bounds[1];
    const int len = ghi - glo;
    const int lo = glo + (len * (int)rank) / CSZ;
    const int hi = glo + (len * ((int)rank + 1)) / CSZ;
    const float4* __restrict__ base = in4 + lane;

    // ---- Phase A: accumulate partial stats over my quarter (unroll x2) ----
    float q0 = 0.f, q1 = 0.f, q2 = 0.f, q3 = 0.f;
    float s0 = 0.f, s1 = 0.f, s2 = 0.f, s3 = 0.f;
    int n = lo + row;
    for (; n + ROWS < hi; n += 2 * ROWS) {
        float4 xa = __ldg(base + (size_t)n * V);
        float4 xb = __ldg(base + (size_t)(n + ROWS) * V);
        q0 = fmaf(xa.x, xa.x, q0); q1 = fmaf(xa.y, xa.y, q1);
        q2 = fmaf(xa.z, xa.z, q2); q3 = fmaf(xa.w, xa.w, q3);
        q0 = fmaf(xb.x, xb.x, q0); q1 = fmaf(xb.y, xb.y, q1);
        q2 = fmaf(xb.z, xb.z, q2); q3 = fmaf(xb.w, xb.w, q3);
        if (sc) {
            s0 += xa.x + xb.x; s1 += xa.y + xb.y;
            s2 += xa.z + xb.z; s3 += xa.w + xb.w;
        }
    }
    if (n < hi) {
        float4 x = __ldg(base + (size_t)n * V);
        q0 = fmaf(x.x, x.x, q0); q1 = fmaf(x.y, x.y, q1);
        q2 = fmaf(x.z, x.z, q2); q3 = fmaf(x.w, x.w, q3);
        if (sc) { s0 += x.x; s1 += x.y; s2 += x.z; s3 += x.w; }
    }
    atomicAdd(&s_sq[col0 + 0], q0); atomicAdd(&s_sq[col0 + 1], q1);
    atomicAdd(&s_sq[col0 + 2], q2); atomicAdd(&s_sq[col0 + 3], q3);
    if (sc) {
        atomicAdd(&s_sum[col0 + 0], s0); atomicAdd(&s_sum[col0 + 1], s1);
        atomicAdd(&s_sum[col0 + 2], s2); atomicAdd(&s_sum[col0 + 3], s3);
    }

    // ---- Combine partials across the 4-CTA cluster ----
    cluster.sync();   // all ranks' partial stats visible cluster-wide

    if (tid < NCH) {
        const int t = tid;
        const float cntf = fmaxf((float)len, 1.0f);
        float scale, beta;
        if (t < NSC) {
            float sm = 0.f, sq = 0.f;
            for (int r = 0; r < CSZ; r++) {
                sm += cluster.map_shared_rank(s_sum, r)[t];
                sq += cluster.map_shared_rank(s_sq,  r)[t];
            }
            float mean = sm / cntf;
            float var  = fmaxf(sq / cntf - mean * mean, 0.0f);
            scale = rsqrtf(var + EPSV) * w[t];
            beta  = bias[t] - mean * scale;
        } else if (t < 192) {
            int b0 = 128 + (t - 128) * 3;
            float sq = 0.f;
            for (int r = 0; r < CSZ; r++) {
                const float* p = cluster.map_shared_rank(s_sq, r);
                sq += p[b0] + p[b0 + 1] + p[b0 + 2];
            }
            scale = rsqrtf(sq / (3.0f * cntf) + EPSV) * w[t];
            beta  = 0.f;
        } else {
            int b0 = 320 + (t - 192) * 5;
            float sq = 0.f;
            for (int r = 0; r < CSZ; r++) {
                const float* p = cluster.map_shared_rank(s_sq, r);
                sq += p[b0] + p[b0 + 1] + p[b0 + 2] + p[b0 + 3] + p[b0 + 4];
            }
            scale = rsqrtf(sq / (5.0f * cntf) + EPSV) * w[t];
            beta  = 0.f;
        }
        s_scale[t] = scale;
        s_beta[t]  = beta;
    }

    // Params only need block-local visibility; s_sq is read-only from here.
    __syncthreads();

    // ---- Phase B: apply over my quarter in REVERSE order (newest L2 lines
    //      first); reads __ldcs (evict-first), writes __stcs (streaming) ----
    const float4 scv = make_float4(s_scale[c0], s_scale[c1], s_scale[c2], s_scale[c3]);
    const float4 btv = make_float4(s_beta[c0],  s_beta[c1],  s_beta[c2],  s_beta[c3]);
    float4* __restrict__ obase = out4 + lane;
    const int first = lo + row;
    if (first < hi) {
        // largest n < hi with n ≡ first (mod ROWS)
        n = hi - 1 - ((hi - 1 - first) % ROWS);
        for (; n - ROWS >= first; n -= 2 * ROWS) {
            float4 xa = __ldcs(base + (size_t)n * V);
            float4 xb = __ldcs(base + (size_t)(n - ROWS) * V);
            float4 oa, ob;
            oa.x = fmaf(xa.x, scv.x, btv.x); oa.y = fmaf(xa.y, scv.y, btv.y);
            oa.z = fmaf(xa.z, scv.z, btv.z); oa.w = fmaf(xa.w, scv.w, btv.w);
            ob.x = fmaf(xb.x, scv.x, btv.x); ob.y = fmaf(xb.y, scv.y, btv.y);
            ob.z = fmaf(xb.z, scv.z, btv.z); ob.w = fmaf(xb.w, scv.w, btv.w);
            __stcs(obase + (size_t)n * V, oa);
            __stcs(obase + (size_t)(n - ROWS) * V, ob);
        }
        if (n >= first) {
            float4 x = __ldcs(base + (size_t)n * V);
            float4 o;
            o.x = fmaf(x.x, scv.x, btv.x); o.y = fmaf(x.y, scv.y, btv.y);
            o.z = fmaf(x.z, scv.z, btv.z); o.w = fmaf(x.w, scv.w, btv.w);
            __stcs(obase + (size_t)n * V, o);
        }
    }

    // SMEM-lifetime safety: peers' DSMEM reads of my partials must complete
    // before my SMEM is recycled. All quarters finish nearly together.
    cluster.sync();
}

// ---------------------------------------------------------------------------
extern "C" void kernel_launch(void* const* d_in, const int* in_sizes, int n_in,
                              void* d_out, int out_size)
{
    const float* inp   = (const float*)d_in[0];   // (N, 480) f32
    const float* w     = (const float*)d_in[1];   // (224,)   f32
    const float* bias  = (const float*)d_in[2];   // (128,)   f32
    const void*  batch = (const void*)d_in[3];    // (N,) int32 or int64, sorted
    float*       out   = (float*)d_out;

    const int N = in_sizes[0] / DIM;              // dtype-independent node count

    fused_kernel<<<NG * CSZ, TPB>>>((const float4*)inp, (float4*)out,
                                    w, bias, batch, N);
}

// round 16
// speedup vs baseline: 1.0907x; 1.0644x over previous
#include <cuda_runtime.h>
#include <cooperative_groups.h>

namespace cg = cooperative_groups;

#define NG   512      // number of graphs
#define DIM  480      // feature dim
#define V    120      // float4 groups per row
#define NCH  224      // total channels (128 scalar + 64 l1 + 32 l2)
#define NSC  128      // scalar channels
#define EPSV 1e-5f
#define TPB  480      // 4 node-rows x 120 float4 lanes
#define ROWS 4
#define CSZ  4        // CTAs per cluster (one graph per cluster)

__device__ __forceinline__ int col_channel(int col) {
    if (col < 128) return col;                       // l=0
    if (col < 320) return 128 + (col - 128) / 3;     // l=1 (d=3)
    return 192 + (col - 320) / 5;                    // l=2 (d=5)
}

// Read batch id for node n under either dtype interpretation.
__device__ __forceinline__ int read_g(const void* __restrict__ b, int n, int is64) {
    if (is64) return (int)__ldg(((const long long*)b) + n);
    return __ldg(((const int*)b) + n);
}

// batch sorted in [0, NG); N even. 32-bit word [N-1] is an odd index:
// int64 buffer -> high half == 0 ; int32 buffer -> batch[N-1] > 0 (w.p. ~1).
__device__ __forceinline__ int detect_is64(const void* __restrict__ b, int N) {
    return (__ldg(((const int*)b) + (N - 1)) == 0) ? 1 : 0;
}

// Warp-collective 32-ary lower bound: first index n with batch[n] >= key.
// ~log33(N) ballot levels + one 32-wide linear step = ~4 dependent
// memory round-trips (vs 18 for scalar binary search — R15's stall source).
__device__ __forceinline__ int warp_lower_bound(const void* __restrict__ b,
                                                int N, int key, int is64,
                                                int lane) {
    int lo = 0, hi = N;                 // answer in [lo, hi]
    while (hi - lo > 32) {
        long long span = hi - lo;
        int pos = lo + (int)((span * (lane + 1)) / 33);
        bool less = read_g(b, pos, is64) < key;      // answer > pos
        unsigned m = __ballot_sync(0xffffffffu, less);
        int cnt = __popc(m);            // probes with value < key
        int nlo = (cnt == 0)  ? lo : lo + (int)((span * cnt) / 33) + 1;
        int nhi = (cnt == 32) ? hi : lo + (int)((span * (cnt + 1)) / 33) + 1;
        lo = nlo;
        hi = (nhi < hi) ? nhi : hi;
    }
    int pos = lo + lane;
    bool ge = (pos < hi) ? (read_g(b, pos, is64) >= key) : true;
    unsigned m = __ballot_sync(0xffffffffu, ge);
    return lo + (__ffs(m) - 1);
}

// ---------------------------------------------------------------------------
// Fused, 4-CTA clustered, occupancy-2 — the R10 optimum (T_A ~ 11us < L2
// turnover -> phase-B re-reads L2-hit; occ=2 + unroll x2 = 30KB/SM in
// flight covering DRAM latency) with the prep kernel folded in as a
// warp-parallel 32-ary search (~0.5us, vs R15's scalar search that stalled
// each CTA ~3us). Phase B is FORWARD order (R15's reverse bought nothing).
// Stores are __stcs (R11: __stwt breaks write-combining, +250MB RMW).
// ---------------------------------------------------------------------------
__global__ __launch_bounds__(TPB, 2) __cluster_dims__(CSZ, 1, 1)
void fused_kernel(
    const float4* __restrict__ in4, float4* __restrict__ out4,
    const float* __restrict__ w, const float* __restrict__ bias,
    const void* __restrict__ batch, int N)
{
    __shared__ float s_sq[DIM];             // per-column partial sum of squares
    __shared__ float s_sum[NSC];            // per-column partial sum (scalars)
    __shared__ float s_scale[NCH], s_beta[NCH];
    __shared__ int s_bounds[2];             // glo, ghi for my graph

    cg::cluster_group cluster = cg::this_cluster();
    const unsigned rank = cluster.block_rank();   // 0..3
    const int g    = blockIdx.x / CSZ;
    const int tid  = threadIdx.x;
    const int lane = tid % V;
    const int row  = tid / V;
    const int col0 = lane * 4;
    const int c0 = col_channel(col0),     c1 = col_channel(col0 + 1);
    const int c2 = col_channel(col0 + 2), c3 = col_channel(col0 + 3);
    const bool sc = (col0 < NSC);

    // Graph bounds: warp 0 searches g, warp 1 searches g+1 (concurrent).
    if (tid < 64) {
        int wl   = tid & 31;
        int widx = tid >> 5;          // 0 or 1
        int is64 = detect_is64(batch, N);
        int r = warp_lower_bound(batch, N, g + widx, is64, wl);
        if (wl == 0) s_bounds[widx] = r;
    }
    for (int i = tid; i < DIM; i += TPB) s_sq[i] = 0.f;
    for (int i = tid; i < NSC; i += TPB) s_sum[i] = 0.f;
    __syncthreads();

    const int glo = s_bounds[0], ghi = s_bounds[1];
    const int len = ghi - glo;
    const int lo = glo + (len * (int)rank) / CSZ;
    const int hi = glo + (len * ((int)rank + 1)) / CSZ;
    const float4* __restrict__ base = in4 + lane;

    // ---- Phase A: accumulate partial stats over my quarter (unroll x2) ----
    float q0 = 0.f, q1 = 0.f, q2 = 0.f, q3 = 0.f;
    float s0 = 0.f, s1 = 0.f, s2 = 0.f, s3 = 0.f;
    int n = lo + row;
    for (; n + ROWS < hi; n += 2 * ROWS) {
        float4 xa = __ldg(base + (size_t)n * V);
        float4 xb = __ldg(base + (size_t)(n + ROWS) * V);
        q0 = fmaf(xa.x, xa.x, q0); q1 = fmaf(xa.y, xa.y, q1);
        q2 = fmaf(xa.z, xa.z, q2); q3 = fmaf(xa.w, xa.w, q3);
        q0 = fmaf(xb.x, xb.x, q0); q1 = fmaf(xb.y, xb.y, q1);
        q2 = fmaf(xb.z, xb.z, q2); q3 = fmaf(xb.w, xb.w, q3);
        if (sc) {
            s0 += xa.x + xb.x; s1 += xa.y + xb.y;
            s2 += xa.z + xb.z; s3 += xa.w + xb.w;
        }
    }
    if (n < hi) {
        float4 x = __ldg(base + (size_t)n * V);
        q0 = fmaf(x.x, x.x, q0); q1 = fmaf(x.y, x.y, q1);
        q2 = fmaf(x.z, x.z, q2); q3 = fmaf(x.w, x.w, q3);
        if (sc) { s0 += x.x; s1 += x.y; s2 += x.z; s3 += x.w; }
    }
    atomicAdd(&s_sq[col0 + 0], q0); atomicAdd(&s_sq[col0 + 1], q1);
    atomicAdd(&s_sq[col0 + 2], q2); atomicAdd(&s_sq[col0 + 3], q3);
    if (sc) {
        atomicAdd(&s_sum[col0 + 0], s0); atomicAdd(&s_sum[col0 + 1], s1);
        atomicAdd(&s_sum[col0 + 2], s2); atomicAdd(&s_sum[col0 + 3], s3);
    }

    // ---- Combine partials across the 4-CTA cluster ----
    cluster.sync();   // all ranks' partial stats visible cluster-wide

    if (tid < NCH) {
        const int t = tid;
        const float cntf = fmaxf((float)len, 1.0f);
        float scale, beta;
        if (t < NSC) {
            float sm = 0.f, sq = 0.f;
            for (int r = 0; r < CSZ; r++) {
                sm += cluster.map_shared_rank(s_sum, r)[t];
                sq += cluster.map_shared_rank(s_sq,  r)[t];
            }
            float mean = sm / cntf;
            float var  = fmaxf(sq / cntf - mean * mean, 0.0f);
            scale = rsqrtf(var + EPSV) * w[t];
            beta  = bias[t] - mean * scale;
        } else if (t < 192) {
            int b0 = 128 + (t - 128) * 3;
            float sq = 0.f;
            for (int r = 0; r < CSZ; r++) {
                const float* p = cluster.map_shared_rank(s_sq, r);
                sq += p[b0] + p[b0 + 1] + p[b0 + 2];
            }
            scale = rsqrtf(sq / (3.0f * cntf) + EPSV) * w[t];
            beta  = 0.f;
        } else {
            int b0 = 320 + (t - 192) * 5;
            float sq = 0.f;
            for (int r = 0; r < CSZ; r++) {
                const float* p = cluster.map_shared_rank(s_sq, r);
                sq += p[b0] + p[b0 + 1] + p[b0 + 2] + p[b0 + 3] + p[b0 + 4];
            }
            scale = rsqrtf(sq / (5.0f * cntf) + EPSV) * w[t];
            beta  = 0.f;
        }
        s_scale[t] = scale;
        s_beta[t]  = beta;
    }

    // Params only need block-local visibility; s_sq is read-only from here.
    __syncthreads();

    // ---- Phase B: apply over my quarter, FORWARD order (reads L2-hot via
    //      __ldcs evict-first; writes __stcs streaming) ----
    const float4 scv = make_float4(s_scale[c0], s_scale[c1], s_scale[c2], s_scale[c3]);
    const float4 btv = make_float4(s_beta[c0],  s_beta[c1],  s_beta[c2],  s_beta[c3]);
    float4* __restrict__ obase = out4 + lane;
    n = lo + row;
    for (; n + ROWS < hi; n += 2 * ROWS) {
        float4 xa = __ldcs(base + (size_t)n * V);
        float4 xb = __ldcs(base + (size_t)(n + ROWS) * V);
        float4 oa, ob;
        oa.x = fmaf(xa.x, scv.x, btv.x); oa.y = fmaf(xa.y, scv.y, btv.y);
        oa.z = fmaf(xa.z, scv.z, btv.z); oa.w = fmaf(xa.w, scv.w, btv.w);
        ob.x = fmaf(xb.x, scv.x, btv.x); ob.y = fmaf(xb.y, scv.y, btv.y);
        ob.z = fmaf(xb.z, scv.z, btv.z); ob.w = fmaf(xb.w, scv.w, btv.w);
        __stcs(obase + (size_t)n * V, oa);
        __stcs(obase + (size_t)(n + ROWS) * V, ob);
    }
    if (n < hi) {
        float4 x = __ldcs(base + (size_t)n * V);
        float4 o;
        o.x = fmaf(x.x, scv.x, btv.x); o.y = fmaf(x.y, scv.y, btv.y);
        o.z = fmaf(x.z, scv.z, btv.z); o.w = fmaf(x.w, scv.w, btv.w);
        __stcs(obase + (size_t)n * V, o);
    }

    // SMEM-lifetime safety: peers' DSMEM reads of my partials must complete
    // before my SMEM is recycled. All quarters finish nearly together.
    cluster.sync();
}

// ---------------------------------------------------------------------------
extern "C" void kernel_launch(void* const* d_in, const int* in_sizes, int n_in,
                              void* d_out, int out_size)
{
    const float* inp   = (const float*)d_in[0];   // (N, 480) f32
    const float* w     = (const float*)d_in[1];   // (224,)   f32
    const float* bias  = (const float*)d_in[2];   // (128,)   f32
    const void*  batch = (const void*)d_in[3];    // (N,) int32 or int64, sorted
    float*       out   = (float*)d_out;

    const int N = in_sizes[0] / DIM;              // dtype-independent node count

    fused_kernel<<<NG * CSZ, TPB>>>((const float4*)inp, (float4*)out,
                                    w, bias, batch, N);
}

// round 17
// speedup vs baseline: 1.1632x; 1.0664x over previous
#include <cuda_runtime.h>
#include <cooperative_groups.h>

namespace cg = cooperative_groups;

#define NG   512      // number of graphs
#define DIM  480      // feature dim
#define V    120      // float4 groups per row
#define NCH  224      // total channels (128 scalar + 64 l1 + 32 l2)
#define NSC  128      // scalar channels
#define EPSV 1e-5f
#define TPB  480      // 4 node-rows x 120 float4 lanes
#define ROWS 4
#define CSZ  4        // CTAs per cluster (one graph per cluster)

__device__ int g_off[NG + 1];   // g_off[g] = first node index with batch >= g

__device__ __forceinline__ int col_channel(int col) {
    if (col < 128) return col;                       // l=0
    if (col < 320) return 128 + (col - 128) / 3;     // l=1 (d=3)
    return 192 + (col - 320) / 5;                    // l=2 (d=5)
}

// Read batch id for node n under either dtype interpretation.
__device__ __forceinline__ int read_g(const void* __restrict__ b, int n, int is64) {
    if (is64) return (int)((const long long*)b)[n];
    return ((const int*)b)[n];
}

// batch sorted in [0, NG); N even. 32-bit word [N-1] is an odd index:
// int64 buffer -> high half == 0 ; int32 buffer -> batch[N-1] > 0 (w.p. ~1).
__device__ __forceinline__ int detect_is64(const void* __restrict__ b, int N) {
    return (((const int*)b)[N - 1] == 0) ? 1 : 0;
}

// ---------------------------------------------------------------------------
// Prep: boundary scan of sorted batch -> segment offsets g_off[0..NG].
// Cost paid ONCE (R15/R16 proved per-CTA in-kernel search repeats its serial
// latency every CTA x 6.7 waves and costs ~16us of fused time).
// ---------------------------------------------------------------------------
__global__ void prep_kernel(const void* __restrict__ batch, int N) {
    const int is64 = detect_is64(batch, N);
    for (int n = blockIdx.x * blockDim.x + threadIdx.x; n < N;
         n += gridDim.x * blockDim.x) {
        int gn = read_g(batch, n, is64);
        if (n == 0) {
            for (int g = 0; g <= gn; g++) g_off[g] = 0;
        } else {
            int gp = read_g(batch, n - 1, is64);
            for (int g = gp + 1; g <= gn; g++) g_off[g] = n;
        }
        if (n == N - 1) {
            for (int g = gn + 1; g <= NG; g++) g_off[g] = N;
        }
    }
}

// ---------------------------------------------------------------------------
// Fused, 4-CTA clustered, occupancy-2 — the R10 optimum: T_A = slab/(SM_BW/
// occ) ~ 11us < L2 turnover (~20-25us) so phase-B re-reads are L2-hot;
// occ=2 + unroll x2 keeps 30KB/SM of loads in flight covering DRAM latency.
// PDL: launched with programmatic stream serialization; the CTA prologue
// (smem zero) overlaps the prep kernel, and cudaGridDependencySynchronize()
// blocks only right before g_off is consumed.
// Stores are __stcs (R11: __stwt breaks write-combining, +250MB RMW).
// ---------------------------------------------------------------------------
__global__ __launch_bounds__(TPB, 2) __cluster_dims__(CSZ, 1, 1)
void fused_kernel(
    const float4* __restrict__ in4, float4* __restrict__ out4,
    const float* __restrict__ w, const float* __restrict__ bias)
{
    __shared__ float s_sq[DIM];             // per-column partial sum of squares
    __shared__ float s_sum[NSC];            // per-column partial sum (scalars)
    __shared__ float s_scale[NCH], s_beta[NCH];
    __shared__ int s_range[4];              // mylo, myhi, glo, ghi

    cg::cluster_group cluster = cg::this_cluster();
    const unsigned rank = cluster.block_rank();   // 0..3
    const int g    = blockIdx.x / CSZ;
    const int tid  = threadIdx.x;
    const int lane = tid % V;
    const int row  = tid / V;
    const int col0 = lane * 4;
    const int c0 = col_channel(col0),     c1 = col_channel(col0 + 1);
    const int c2 = col_channel(col0 + 2), c3 = col_channel(col0 + 3);
    const bool sc = (col0 < NSC);

    // Prologue overlaps the prep kernel under PDL.
    for (int i = tid; i < DIM; i += TPB) s_sq[i] = 0.f;
    for (int i = tid; i < NSC; i += TPB) s_sum[i] = 0.f;

#if __CUDA_ARCH__ >= 900
    cudaGridDependencySynchronize();   // wait for prep's g_off before use
#endif
    if (tid == 0) {
        int glo = g_off[g], ghi = g_off[g + 1];
        int len = ghi - glo;
        s_range[0] = glo + (len * (int)rank) / CSZ;
        s_range[1] = glo + (len * ((int)rank + 1)) / CSZ;
        s_range[2] = glo;
        s_range[3] = ghi;
    }
    __syncthreads();

    const int lo = s_range[0], hi = s_range[1];
    const float4* __restrict__ base = in4 + lane;

    // ---- Phase A: accumulate partial stats over my quarter (unroll x2) ----
    float q0 = 0.f, q1 = 0.f, q2 = 0.f, q3 = 0.f;
    float s0 = 0.f, s1 = 0.f, s2 = 0.f, s3 = 0.f;
    int n = lo + row;
    for (; n + ROWS < hi; n += 2 * ROWS) {
        float4 xa = __ldg(base + (size_t)n * V);
        float4 xb = __ldg(base + (size_t)(n + ROWS) * V);
        q0 = fmaf(xa.x, xa.x, q0); q1 = fmaf(xa.y, xa.y, q1);
        q2 = fmaf(xa.z, xa.z, q2); q3 = fmaf(xa.w, xa.w, q3);
        q0 = fmaf(xb.x, xb.x, q0); q1 = fmaf(xb.y, xb.y, q1);
        q2 = fmaf(xb.z, xb.z, q2); q3 = fmaf(xb.w, xb.w, q3);
        if (sc) {
            s0 += xa.x + xb.x; s1 += xa.y + xb.y;
            s2 += xa.z + xb.z; s3 += xa.w + xb.w;
        }
    }
    if (n < hi) {
        float4 x = __ldg(base + (size_t)n * V);
        q0 = fmaf(x.x, x.x, q0); q1 = fmaf(x.y, x.y, q1);
        q2 = fmaf(x.z, x.z, q2); q3 = fmaf(x.w, x.w, q3);
        if (sc) { s0 += x.x; s1 += x.y; s2 += x.z; s3 += x.w; }
    }
    atomicAdd(&s_sq[col0 + 0], q0); atomicAdd(&s_sq[col0 + 1], q1);
    atomicAdd(&s_sq[col0 + 2], q2); atomicAdd(&s_sq[col0 + 3], q3);
    if (sc) {
        atomicAdd(&s_sum[col0 + 0], s0); atomicAdd(&s_sum[col0 + 1], s1);
        atomicAdd(&s_sum[col0 + 2], s2); atomicAdd(&s_sum[col0 + 3], s3);
    }

    // ---- Combine partials across the 4-CTA cluster ----
    cluster.sync();   // all ranks' partial stats visible cluster-wide

    if (tid < NCH) {
        const int t = tid;
        const float cntf = fmaxf((float)(s_range[3] - s_range[2]), 1.0f);
        float scale, beta;
        if (t < NSC) {
            float sm = 0.f, sq = 0.f;
            for (int r = 0; r < CSZ; r++) {
                sm += cluster.map_shared_rank(s_sum, r)[t];
                sq += cluster.map_shared_rank(s_sq,  r)[t];
            }
            float mean = sm / cntf;
            float var  = fmaxf(sq / cntf - mean * mean, 0.0f);
            scale = rsqrtf(var + EPSV) * w[t];
            beta  = bias[t] - mean * scale;
        } else if (t < 192) {
            int b0 = 128 + (t - 128) * 3;
            float sq = 0.f;
            for (int r = 0; r < CSZ; r++) {
                const float* p = cluster.map_shared_rank(s_sq, r);
                sq += p[b0] + p[b0 + 1] + p[b0 + 2];
            }
            scale = rsqrtf(sq / (3.0f * cntf) + EPSV) * w[t];
            beta  = 0.f;
        } else {
            int b0 = 320 + (t - 192) * 5;
            float sq = 0.f;
            for (int r = 0; r < CSZ; r++) {
                const float* p = cluster.map_shared_rank(s_sq, r);
                sq += p[b0] + p[b0 + 1] + p[b0 + 2] + p[b0 + 3] + p[b0 + 4];
            }
            scale = rsqrtf(sq / (5.0f * cntf) + EPSV) * w[t];
            beta  = 0.f;
        }
        s_scale[t] = scale;
        s_beta[t]  = beta;
    }

    // Params only need block-local visibility; s_sq is read-only from here.
    __syncthreads();

    // ---- Phase B: apply over my quarter, FORWARD order (reads L2-hot via
    //      __ldcs evict-first; writes __stcs streaming) ----
    const float4 scv = make_float4(s_scale[c0], s_scale[c1], s_scale[c2], s_scale[c3]);
    const float4 btv = make_float4(s_beta[c0],  s_beta[c1],  s_beta[c2],  s_beta[c3]);
    float4* __restrict__ obase = out4 + lane;
    n = lo + row;
    for (; n + ROWS < hi; n += 2 * ROWS) {
        float4 xa = __ldcs(base + (size_t)n * V);
        float4 xb = __ldcs(base + (size_t)(n + ROWS) * V);
        float4 oa, ob;
        oa.x = fmaf(xa.x, scv.x, btv.x); oa.y = fmaf(xa.y, scv.y, btv.y);
        oa.z = fmaf(xa.z, scv.z, btv.z); oa.w = fmaf(xa.w, scv.w, btv.w);
        ob.x = fmaf(xb.x, scv.x, btv.x); ob.y = fmaf(xb.y, scv.y, btv.y);
        ob.z = fmaf(xb.z, scv.z, btv.z); ob.w = fmaf(xb.w, scv.w, btv.w);
        __stcs(obase + (size_t)n * V, oa);
        __stcs(obase + (size_t)(n + ROWS) * V, ob);
    }
    if (n < hi) {
        float4 x = __ldcs(base + (size_t)n * V);
        float4 o;
        o.x = fmaf(x.x, scv.x, btv.x); o.y = fmaf(x.y, scv.y, btv.y);
        o.z = fmaf(x.z, scv.z, btv.z); o.w = fmaf(x.w, scv.w, btv.w);
        __stcs(obase + (size_t)n * V, o);
    }

    // SMEM-lifetime safety: peers' DSMEM reads of my partials must complete
    // before my SMEM is recycled. All quarters finish nearly together.
    cluster.sync();
}

// ---------------------------------------------------------------------------
extern "C" void kernel_launch(void* const* d_in, const int* in_sizes, int n_in,
                              void* d_out, int out_size)
{
    const float* inp   = (const float*)d_in[0];   // (N, 480) f32
    const float* w     = (const float*)d_in[1];   // (224,)   f32
    const float* bias  = (const float*)d_in[2];   // (128,)   f32
    const void*  batch = (const void*)d_in[3];    // (N,) int32 or int64, sorted
    float*       out   = (float*)d_out;

    const int N = in_sizes[0] / DIM;              // dtype-independent node count

    prep_kernel<<<304, 256>>>(batch, N);

    // PDL launch: fused starts while prep drains; dependency enforced at
    // cudaGridDependencySynchronize() inside the kernel.
    cudaLaunchConfig_t cfg = {};
    cfg.gridDim  = dim3(NG * CSZ, 1, 1);
    cfg.blockDim = dim3(TPB, 1, 1);
    cudaLaunchAttribute attrs[1];
    attrs[0].id = cudaLaunchAttributeProgrammaticStreamSerialization;
    attrs[0].val.programmaticStreamSerializationAllowed = 1;
    cfg.attrs = attrs;
    cfg.numAttrs = 1;

    cudaError_t e = cudaLaunchKernelEx(&cfg, fused_kernel,
                                       (const float4*)inp, (float4*)out,
                                       w, bias);
    if (e != cudaSuccess) {
        (void)cudaGetLastError();   // clear; fall back to plain launch
        fused_kernel<<<NG * CSZ, TPB>>>((const float4*)inp, (float4*)out,
                                        w, bias);
    }
}